// round 11
// baseline (speedup 1.0000x reference)
#include <cuda_runtime.h>
#include <cuda_bf16.h>
#include <math.h>
#include <stdint.h>

#define Bc 4
#define Sc 2048
#define Hc 1024
#define INNERc 512
#define Rc 8

// ---------------- scratch (device globals; no allocation allowed) ----------
__device__ float g_q[Bc * Sc * Hc];      // 32 MB
__device__ float g_state[Bc * Sc * Hc];  // 32 MB (ping)
__device__ float g_tmp[Bc * Sc * Hc];    // 32 MB (pong)
__device__ float g_mu[Bc * Sc * Rc];
__device__ float g_invs[Bc * Sc];
__device__ float g_dots[Bc * Sc * 9];
__device__ float g_energy[Bc];
// bf16 hi/lo split operands: per 16-k chunk, 32 bf16 = [hi16 | lo16]
__device__ __nv_bfloat16 g_Acat[(size_t)Bc * Sc * 2 * Hc];  // [8192][2048]
__device__ __nv_bfloat16 g_Wt[(size_t)Hc * 2 * Hc];         // [1024][2048] (W^T)

__device__ __forceinline__ uint32_t bf2pack(__nv_bfloat16 a, __nv_bfloat16 b) {
    __nv_bfloat162 p = __halves2bfloat162(a, b);
    return *reinterpret_cast<uint32_t*>(&p);
}

#define CP16(dst_u32, src_ptr)                                                 \
    asm volatile("cp.async.ca.shared.global [%0], [%1], 16;"                   \
                 :: "r"(dst_u32), "l"(src_ptr))
#define CPCOMMIT() asm volatile("cp.async.commit_group;")
#define CPWAIT1() asm volatile("cp.async.wait_group 1;")
#define CPWAIT0() asm volatile("cp.async.wait_group 0;")

// ---------------- prep: copy hidden->state AND build bf16 hi/lo split -------
__global__ void prep_kernel(const float* __restrict__ hidden) {
    size_t idx = (size_t)blockIdx.x * 256 + threadIdx.x;   // 8192*256
    int r = (int)(idx >> 8);
    int qq = (int)(idx & 255);
    int ch = qq >> 2, c4 = (qq & 3) * 4;     // 64 chunks of 16 k, 4 floats each
    size_t goff = (size_t)r * Hc + ch * 16 + c4;
    float4 v = *(const float4*)&hidden[goff];
    *(float4*)&g_state[goff] = v;
    float vv[4] = {v.x, v.y, v.z, v.w};
    __nv_bfloat16 h[4], l[4];
#pragma unroll
    for (int j = 0; j < 4; ++j) {
        h[j] = __float2bfloat16_rn(vv[j]);
        l[j] = __float2bfloat16_rn(vv[j] - __bfloat162float(h[j]));
    }
    size_t base = (size_t)r * 2048 + ch * 32;
    *(uint32_t*)&g_Acat[base + c4]          = bf2pack(h[0], h[1]);
    *(uint32_t*)&g_Acat[base + c4 + 2]      = bf2pack(h[2], h[3]);
    *(uint32_t*)&g_Acat[base + 16 + c4]     = bf2pack(l[0], l[1]);
    *(uint32_t*)&g_Acat[base + 16 + c4 + 2] = bf2pack(l[2], l[3]);
}

__global__ void zero_energy_kernel() {
    if (threadIdx.x < Bc) g_energy[threadIdx.x] = 0.f;
}

// ---------------- Wq transpose + hi/lo split --------------------------------
__global__ void convertW_kernel(const float* __restrict__ W) {
    __shared__ float tile[32][33];
    int kb = blockIdx.x, nb = blockIdx.y;
    int tx = threadIdx.x & 31, ty = threadIdx.x >> 5;   // 32 x 8
#pragma unroll
    for (int j = 0; j < 4; ++j) {
        int k = ty + j * 8;
        tile[k][tx] = W[(size_t)(kb * 32 + k) * Hc + nb * 32 + tx];
    }
    __syncthreads();
#pragma unroll
    for (int j = 0; j < 4; ++j) {
        int n = ty + j * 8;
        float x = tile[tx][n];
        __nv_bfloat16 h = __float2bfloat16_rn(x);
        __nv_bfloat16 l = __float2bfloat16_rn(x - __bfloat162float(h));
        int ch = kb * 2 + (tx >> 4), kin = tx & 15;
        size_t base = (size_t)(nb * 32 + n) * 2048 + (size_t)ch * 32 + kin;
        g_Wt[base]      = h;
        g_Wt[base + 16] = l;
    }
}

// ---------------- GEMM v3: 128x64 tile, 256 thr, cp.async 2-stage -----------
#define BM3 128
#define BN3 64
#define ST3 40   // smem row stride (bf16), conflict-free fragment loads
__global__ void __launch_bounds__(256) gemm_mma_kernel(const float* __restrict__ bias) {
    __shared__ __nv_bfloat16 sA[2][BM3 * ST3];   // 2 x 10.0 KB
    __shared__ __nv_bfloat16 sB[2][BN3 * ST3];   // 2 x 5.0 KB
    int tid = threadIdx.x;
    int wid = tid >> 5, lane = tid & 31;
    int g = lane >> 2, tg = lane & 3;
    int wm = wid & 3, wn = wid >> 2;             // 4 x 2 warps, warp tile 32x32
    int m0 = blockIdx.y * BM3, n0 = blockIdx.x * BN3;
    float acc[2][4][4] = {};

    // staging coords
    int rA = tid >> 1, cA = (tid & 1) * 16;      // 128 rows x {0,16}, +8 second op
    int rB = tid >> 2, cB = (tid & 3) * 8;       // 64 rows x {0,8,16,24}
    const __nv_bfloat16* pa = &g_Acat[(size_t)(m0 + rA) * 2048 + cA];
    const __nv_bfloat16* pb = &g_Wt[(size_t)(n0 + rB) * 2048 + cB];
    uint32_t dA0[2], dA1[2], dB0[2];
#pragma unroll
    for (int st = 0; st < 2; ++st) {
        dA0[st] = (uint32_t)__cvta_generic_to_shared(&sA[st][rA * ST3 + cA]);
        dA1[st] = (uint32_t)__cvta_generic_to_shared(&sA[st][rA * ST3 + cA + 8]);
        dB0[st] = (uint32_t)__cvta_generic_to_shared(&sB[st][rB * ST3 + cB]);
    }

    // prologue: stage 0 = chunk 0
    CP16(dA0[0], pa);
    CP16(dA1[0], pa + 8);
    CP16(dB0[0], pb);
    CPCOMMIT();

    for (int ch = 0; ch < 64; ++ch) {
        int st = ch & 1;
        if (ch < 63) {
            int nst = st ^ 1;
            const __nv_bfloat16* na = pa + (size_t)(ch + 1) * 32;
            const __nv_bfloat16* nb = pb + (size_t)(ch + 1) * 32;
            CP16(dA0[nst], na);
            CP16(dA1[nst], na + 8);
            CP16(dB0[nst], nb);
            CPCOMMIT();
            CPWAIT1();
        } else {
            CPWAIT0();
        }
        __syncthreads();

        const __nv_bfloat16* A = sA[st];
        const __nv_bfloat16* B = sB[st];
        uint32_t ah[2][4], al[2][4], bh[4][2], bl[4][2];
#pragma unroll
        for (int mt = 0; mt < 2; ++mt) {
            int row = wm * 32 + mt * 16 + g;
            ah[mt][0] = *(const uint32_t*)&A[row * ST3 + 2 * tg];
            ah[mt][1] = *(const uint32_t*)&A[(row + 8) * ST3 + 2 * tg];
            ah[mt][2] = *(const uint32_t*)&A[row * ST3 + 2 * tg + 8];
            ah[mt][3] = *(const uint32_t*)&A[(row + 8) * ST3 + 2 * tg + 8];
            al[mt][0] = *(const uint32_t*)&A[row * ST3 + 16 + 2 * tg];
            al[mt][1] = *(const uint32_t*)&A[(row + 8) * ST3 + 16 + 2 * tg];
            al[mt][2] = *(const uint32_t*)&A[row * ST3 + 16 + 2 * tg + 8];
            al[mt][3] = *(const uint32_t*)&A[(row + 8) * ST3 + 16 + 2 * tg + 8];
        }
#pragma unroll
        for (int nt = 0; nt < 4; ++nt) {
            int col = wn * 32 + nt * 8 + g;
            bh[nt][0] = *(const uint32_t*)&B[col * ST3 + 2 * tg];
            bh[nt][1] = *(const uint32_t*)&B[col * ST3 + 2 * tg + 8];
            bl[nt][0] = *(const uint32_t*)&B[col * ST3 + 16 + 2 * tg];
            bl[nt][1] = *(const uint32_t*)&B[col * ST3 + 16 + 2 * tg + 8];
        }
#define MMA16(ar, br)                                                          \
    asm volatile("mma.sync.aligned.m16n8k16.row.col.f32.bf16.bf16.f32 "        \
                 "{%0,%1,%2,%3}, {%4,%5,%6,%7}, {%8,%9}, {%0,%1,%2,%3};"       \
                 : "+f"(acc[mt][nt][0]), "+f"(acc[mt][nt][1]),                 \
                   "+f"(acc[mt][nt][2]), "+f"(acc[mt][nt][3])                  \
                 : "r"((ar)[0]), "r"((ar)[1]), "r"((ar)[2]), "r"((ar)[3]),     \
                   "r"((br)[0]), "r"((br)[1]))
#pragma unroll
        for (int mt = 0; mt < 2; ++mt)
#pragma unroll
            for (int nt = 0; nt < 4; ++nt) {
                MMA16(ah[mt], bh[nt]);   // hi*hi
                MMA16(al[mt], bh[nt]);   // lo*hi
                MMA16(ah[mt], bl[nt]);   // hi*lo
            }
#undef MMA16
        __syncthreads();
    }
#pragma unroll
    for (int mt = 0; mt < 2; ++mt)
#pragma unroll
        for (int nt = 0; nt < 4; ++nt) {
            int row = m0 + wm * 32 + mt * 16 + g;
            int col = n0 + wn * 32 + nt * 8 + 2 * tg;
            float2 bi = *(const float2*)&bias[col];
            float2 v0 = {acc[mt][nt][0] + bi.x, acc[mt][nt][1] + bi.y};
            float2 v1 = {acc[mt][nt][2] + bi.x, acc[mt][nt][3] + bi.y};
            *(float2*)&g_q[(size_t)row * Hc + col] = v0;
            *(float2*)&g_q[(size_t)(row + 8) * Hc + col] = v1;
        }
}

// ---------------- dots (initial state only) ---------------------------------
#define DS 32
__global__ void __launch_bounds__(512) dots2_kernel(const float* __restrict__ st) {
    __shared__ float smo[DS + 8][128];
    int blk = blockIdx.x;
    int b = blk >> 6;
    int s0 = (blk & 63) * DS;
    int warp = threadIdx.x >> 5, lane = threadIdx.x & 31;
    int r0 = warp * 2;
    const float* sbase = st + (size_t)b * Sc * Hc;
    float acc[2][9];
#pragma unroll
    for (int rr = 0; rr < 2; ++rr)
#pragma unroll
        for (int d = 0; d < 9; ++d) acc[rr][d] = 0.f;

    for (int hc = 0; hc < Hc / 128; ++hc) {
        int h0 = hc * 128;
        for (int idx = threadIdx.x; idx < (DS + 8) * 32; idx += 512) {
            int r = idx >> 5, c4 = idx & 31;
            int s = s0 + r; if (s >= Sc) s = Sc - 1;
            *(float4*)&smo[r][c4 * 4] =
                *(const float4*)&sbase[(size_t)s * Hc + h0 + c4 * 4];
        }
        __syncthreads();
#pragma unroll
        for (int u = 0; u < 4; ++u) {
            int c = lane + u * 32;
            float xv[10];
#pragma unroll
            for (int t = 0; t < 10; ++t) xv[t] = smo[r0 + t][c];
#pragma unroll
            for (int rr = 0; rr < 2; ++rr)
#pragma unroll
                for (int d = 0; d < 9; ++d)
                    acc[rr][d] = fmaf(xv[rr], xv[rr + d], acc[rr][d]);
        }
        __syncthreads();
    }
#pragma unroll
    for (int rr = 0; rr < 2; ++rr) {
        int i = s0 + r0 + rr;
#pragma unroll
        for (int d = 0; d < 9; ++d) {
            float v = acc[rr][d];
#pragma unroll
            for (int o = 16; o; o >>= 1) v += __shfl_xor_sync(0xffffffffu, v, o);
            if (lane == 0) g_dots[((size_t)b * Sc + i) * 9 + d] = v;
        }
    }
}

// ---------------- mu: one warp per edge -------------------------------------
__global__ void mu_kernel(const float* __restrict__ W1, const float* __restrict__ b1,
                          const float* __restrict__ W2, const float* __restrict__ b2) {
    int gw = (blockIdx.x * blockDim.x + threadIdx.x) >> 5;
    int lane = threadIdx.x & 31;
    if (gw >= Bc * Sc * Rc) return;
    int dm = gw & 7;
    int i = (gw >> 3) % Sc;
    int b = gw / (Rc * Sc);
    int d = dm + 1;
    if (i + d >= Sc) return;
    const float* dots = &g_dots[(size_t)b * Sc * 9];
    float nii = dots[i * 9 + 0];
    float njj = dots[(i + d) * 9 + 0];
    float dij = dots[i * 9 + d];
    float dist = sqrtf(fmaxf(nii + njj - 2.f * dij, 0.f));
    float ni = fmaxf(sqrtf(nii), 1e-6f);
    float nj = fmaxf(sqrtf(njj), 1e-6f);
    float cosv = dij / (ni * nj);
    float acc = 0.f;
#pragma unroll
    for (int u = 0; u < INNERc / 32; ++u) {
        int m = lane + u * 32;
        float x = fmaf(dist, W1[m], fmaf(cosv, W1[INNERc + m], b1[m]));
        float g = 0.5f * x * (1.f + erff(x * 0.70710678118654752f));
        acc = fmaf(g, W2[m], acc);
    }
#pragma unroll
    for (int o = 16; o; o >>= 1) acc += __shfl_xor_sync(0xffffffffu, acc, o);
    if (lane == 0) {
        float z = acc + b2[0];
        float sp = fmaxf(z, 0.f) + log1pf(expf(-fabsf(z)));
        float mu = fminf(sp + 1e-5f, 10.f);
        g_mu[((size_t)b * Sc + i) * Rc + dm] = mu;
    }
}

// ---------------- invs ------------------------------------------------------
__global__ void invs_kernel() {
    int idx = blockIdx.x * blockDim.x + threadIdx.x;
    if (idx >= Bc * Sc) return;
    int b = idx / Sc, i = idx % Sc;
    const float* mu = &g_mu[(size_t)b * Sc * Rc];
    float deg = 0.f;
#pragma unroll
    for (int dm = 0; dm < Rc; ++dm) {
        int d = dm + 1;
        if (i + d < Sc) deg += mu[i * Rc + dm];
        if (i - d >= 0) deg += mu[(i - d) * Rc + dm];
    }
    g_invs[idx] = 1.f / sqrtf(fmaxf(deg, 1e-6f));
}

// ---------------- fused update + smooth + dots (ping-pong) ------------------
// Block owns S-rows [s0, s0+32), loops over all 16 H-chunks of 64.
// Computes t = s - eta*(lap - q) for rows [s0-1, s0+40], smooth for
// [s0, s0+39], writes rows [s0, s0+31], and accumulates the 9 sliding
// dot-products of the smoothed state for its 32 rows.
#define SD 32
__global__ void __launch_bounds__(256) upsm_kernel(const float* __restrict__ sin_,
                                                   float* __restrict__ sout,
                                                   float eta) {
    __shared__ float tile[58][68];   // state rows s0-9 .. s0+48
    __shared__ float tt[42][68];     // t rows s0-1 .. s0+40
    __shared__ float coef[42][16];
    __shared__ float cself[42];
    float (*smo)[68] = tile;         // alias: smoothed rows s0 .. s0+39

    int blk = blockIdx.x;
    int b = blk >> 6;                // 64 chunks per batch
    int s0 = (blk & 63) * SD;
    int warp = threadIdx.x >> 5, lane = threadIdx.x & 31;
    const float* sbase = sin_ + (size_t)b * Sc * Hc;
    const float* qbase = g_q + (size_t)b * Sc * Hc;
    float* obase = sout + (size_t)b * Sc * Hc;
    const float* mu = &g_mu[(size_t)b * Sc * Rc];
    const float* invs = &g_invs[(size_t)b * Sc];

    for (int idx = threadIdx.x; idx < 42 * 16; idx += 256) {
        int tr = idx >> 4, dd = idx & 15;
        int i = s0 - 1 + tr;
        float c = 0.f;
        if (i >= 0 && i < Sc) {
            if (dd < 8) {
                int d = dd + 1;
                if (i + d < Sc) c = mu[i * Rc + dd] * invs[i] * invs[i + d];
            } else {
                int d = dd - 7;
                if (i - d >= 0) c = mu[(i - d) * Rc + (d - 1)] * invs[i] * invs[i - d];
            }
        }
        coef[tr][dd] = c;
    }
    __syncthreads();
    if (threadIdx.x < 42) {
        float s = 0.f;
#pragma unroll
        for (int dd = 0; dd < 16; ++dd) s += coef[threadIdx.x][dd];
        cself[threadIdx.x] = s;
    }

    float acc[4][9];
#pragma unroll
    for (int rr = 0; rr < 4; ++rr)
#pragma unroll
        for (int d = 0; d < 9; ++d) acc[rr][d] = 0.f;
    int r0 = warp * 4;
    int c2 = lane * 2;

    for (int hc = 0; hc < Hc / 64; ++hc) {
        int h0 = hc * 64;
        __syncthreads();   // protect tile (aliased smo) from previous dots reads
        for (int idx = threadIdx.x; idx < 58 * 16; idx += 256) {
            int r = idx >> 4, c4 = (idx & 15) * 4;
            int s = s0 - 9 + r;
            float4 v = make_float4(0.f, 0.f, 0.f, 0.f);
            if (s >= 0 && s < Sc) v = *(const float4*)&sbase[(size_t)s * Hc + h0 + c4];
            *(float4*)&tile[r][c4] = v;
        }
        __syncthreads();
        // t rows
        for (int tr = warp; tr < 42; tr += 8) {
            int i = s0 - 1 + tr;
            float2 t = make_float2(0.f, 0.f);
            if (i >= 0 && i < Sc) {
                float2 s = *(float2*)&tile[tr + 8][c2];
                float2 a = make_float2(0.f, 0.f);
#pragma unroll
                for (int dd = 0; dd < 16; ++dd) {
                    float cf = coef[tr][dd];
                    int roff = (dd < 8) ? (dd + 1) : -(dd - 7);
                    float2 n = *(float2*)&tile[tr + 8 + roff][c2];
                    a.x = fmaf(cf, n.x, a.x);
                    a.y = fmaf(cf, n.y, a.y);
                }
                float cs = cself[tr];
                float2 q = *(const float2*)&qbase[(size_t)i * Hc + h0 + c2];
                t.x = s.x - eta * (cs * s.x - a.x - q.x);
                t.y = s.y - eta * (cs * s.y - a.y - q.y);
            }
            *(float2*)&tt[tr][c2] = t;
        }
        __syncthreads();
        // smooth rows [s0, s0+39] -> smo (alias of tile) + gmem for first 32
        for (int j = warp; j < 40; j += 8) {
            int i = s0 + j;
            int tc = j + 1;
            int tl = (i == 0) ? tc : j;
            int trr = (i == Sc - 1) ? tc : j + 2;
            float2 xc = *(float2*)&tt[tc][c2];
            float2 xl = *(float2*)&tt[tl][c2];
            float2 xr = *(float2*)&tt[trr][c2];
            float2 o;
            o.x = xc.x - 0.1f * (2.f * xc.x - xl.x - xr.x);
            o.y = xc.y - 0.1f * (2.f * xc.y - xl.y - xr.y);
            *(float2*)&smo[j][c2] = o;
            if (j < SD && i < Sc)
                *(float2*)&obase[(size_t)i * Hc + h0 + c2] = o;
        }
        __syncthreads();
        // dots accumulation: warp rows r0..r0+3, columns lane, lane+32
#pragma unroll
        for (int u = 0; u < 2; ++u) {
            int c = lane + u * 32;
            float xv[12];
#pragma unroll
            for (int t = 0; t < 12; ++t) xv[t] = smo[r0 + t][c];
#pragma unroll
            for (int rr = 0; rr < 4; ++rr)
#pragma unroll
                for (int d = 0; d < 9; ++d)
                    acc[rr][d] = fmaf(xv[rr], xv[rr + d], acc[rr][d]);
        }
    }
#pragma unroll
    for (int rr = 0; rr < 4; ++rr) {
        int i = s0 + r0 + rr;
#pragma unroll
        for (int d = 0; d < 9; ++d) {
            float v = acc[rr][d];
#pragma unroll
            for (int o = 16; o; o >>= 1) v += __shfl_xor_sync(0xffffffffu, v, o);
            if (lane == 0) g_dots[((size_t)b * Sc + i) * 9 + d] = v;
        }
    }
}

// ---------------- layernorm(state + hidden) ---------------------------------
__global__ void ln_kernel(const float* __restrict__ hidden,
                          const float* __restrict__ gamma,
                          const float* __restrict__ beta,
                          float* __restrict__ out) {
    int row = blockIdx.x;
    const float* s = g_state + (size_t)row * Hc;
    const float* h = hidden + (size_t)row * Hc;
    int tid = threadIdx.x;
    float v[4];
    float sum = 0.f, ss = 0.f;
#pragma unroll
    for (int k = 0; k < 4; ++k) {
        int c = tid + k * 256;
        float x = s[c] + h[c];
        v[k] = x;
        sum += x;
        ss += x * x;
    }
    __shared__ float r1[8], r2[8];
#pragma unroll
    for (int o = 16; o; o >>= 1) {
        sum += __shfl_xor_sync(0xffffffffu, sum, o);
        ss += __shfl_xor_sync(0xffffffffu, ss, o);
    }
    if ((tid & 31) == 0) { r1[tid >> 5] = sum; r2[tid >> 5] = ss; }
    __syncthreads();
    if (tid < 32) {
        float a = (tid < 8) ? r1[tid] : 0.f;
        float bb = (tid < 8) ? r2[tid] : 0.f;
#pragma unroll
        for (int o = 4; o; o >>= 1) {
            a += __shfl_xor_sync(0xffffffffu, a, o);
            bb += __shfl_xor_sync(0xffffffffu, bb, o);
        }
        if (tid == 0) { r1[0] = a; r2[0] = bb; }
    }
    __syncthreads();
    float mean = r1[0] * (1.f / Hc);
    float var = r2[0] * (1.f / Hc) - mean * mean;
    float is = rsqrtf(var + 1e-5f);
#pragma unroll
    for (int k = 0; k < 4; ++k) {
        int c = tid + k * 256;
        out[(size_t)row * Hc + c] = (v[k] - mean) * is * gamma[c] + beta[c];
    }
}

// ---------------- energy ----------------------------------------------------
__global__ void energy_kernel() {
    int b = blockIdx.y;
    int t = blockIdx.x * blockDim.x + threadIdx.x;
    float e = 0.f;
    if (t < Sc * Rc) {
        int dm = t & 7;
        int i = t >> 3;
        int d = dm + 1;
        if (i + d < Sc) {
            const float* dots = &g_dots[(size_t)b * Sc * 9];
            float diff2 = dots[i * 9] + dots[(i + d) * 9] - 2.f * dots[i * 9 + d];
            e = g_mu[((size_t)b * Sc + i) * Rc + dm] * diff2;
        }
    }
    __shared__ float sred[256];
    sred[threadIdx.x] = e;
    __syncthreads();
    for (int o = 128; o; o >>= 1) {
        if (threadIdx.x < o) sred[threadIdx.x] += sred[threadIdx.x + o];
        __syncthreads();
    }
    if (threadIdx.x == 0) atomicAdd(&g_energy[b], sred[0]);
}

__global__ void finalize_energy_kernel(float* __restrict__ out) {
    if (threadIdx.x < Bc)
        out[(size_t)Bc * Sc * Hc + threadIdx.x] = 0.5f * g_energy[threadIdx.x];
}

// ---------------- launch ----------------------------------------------------
extern "C" void kernel_launch(void* const* d_in, const int* in_sizes, int n_in,
                              void* d_out, int out_size) {
    const float* hidden = (const float*)d_in[0];
    const float* Wq = (const float*)d_in[3];
    const float* bq = (const float*)d_in[4];
    const float* W1 = (const float*)d_in[5];
    const float* b1 = (const float*)d_in[6];
    const float* W2 = (const float*)d_in[7];
    const float* b2 = (const float*)d_in[8];
    const float* gamma = (const float*)d_in[9];
    const float* beta = (const float*)d_in[10];
    float* out = (float*)d_out;

    prep_kernel<<<8192, 256>>>(hidden);
    convertW_kernel<<<dim3(32, 32), 256>>>(Wq);
    gemm_mma_kernel<<<dim3(Hc / BN3, (Bc * Sc) / BM3), 256>>>(bq);

    float* bufA;
    float* bufB;
    cudaGetSymbolAddress((void**)&bufA, g_state);
    cudaGetSymbolAddress((void**)&bufB, g_tmp);
    float* bufs[2] = {bufA, bufB};

    dots2_kernel<<<Bc * (Sc / DS), 512>>>(bufs[0]);
    for (int k = 0; k < 4; ++k) {
        double eta_d = 0.1 * pow(0.9, (double)k);
        float eta = (float)eta_d;
        mu_kernel<<<(Bc * Sc * Rc * 32) / 256, 256>>>(W1, b1, W2, b2);
        invs_kernel<<<(Bc * Sc) / 256, 256>>>();
        upsm_kernel<<<Bc * (Sc / SD), 256>>>(bufs[k & 1], bufs[(k + 1) & 1], eta);
    }

    zero_energy_kernel<<<1, 32>>>();
    energy_kernel<<<dim3((Sc * Rc + 255) / 256, Bc), 256>>>();
    ln_kernel<<<Bc * Sc, 256>>>(hidden, gamma, beta, out);   // final in g_state
    finalize_energy_kernel<<<1, 32>>>(out);
}

// round 16
// speedup vs baseline: 1.2070x; 1.2070x over previous
#include <cuda_runtime.h>
#include <cuda_bf16.h>
#include <math.h>
#include <stdint.h>

#define Bc 4
#define Sc 2048
#define Hc 1024
#define INNERc 512
#define Rc 8

// ---------------- scratch (device globals; no allocation allowed) ----------
__device__ float g_q[Bc * Sc * Hc];      // 32 MB
__device__ float g_state[Bc * Sc * Hc];  // 32 MB (ping)
__device__ float g_tmp[Bc * Sc * Hc];    // 32 MB (pong)
__device__ float g_mu[Bc * Sc * Rc];
__device__ float g_invs[Bc * Sc];
__device__ float g_dots[Bc * Sc * 9];
__device__ float g_energy[Bc];
// bf16 hi/lo split operands: per 32-k chunk, 64 bf16 = [hi32 | lo32]
__device__ __nv_bfloat16 g_Acat[(size_t)Bc * Sc * 2 * Hc];  // [8192][2048]
__device__ __nv_bfloat16 g_Wt[(size_t)Hc * 2 * Hc];         // [1024][2048] (W^T)

__device__ __forceinline__ uint32_t bf2pack(__nv_bfloat16 a, __nv_bfloat16 b) {
    __nv_bfloat162 p = __halves2bfloat162(a, b);
    return *reinterpret_cast<uint32_t*>(&p);
}

#define CP16(dst_u32, src_ptr)                                                 \
    asm volatile("cp.async.ca.shared.global [%0], [%1], 16;"                   \
                 :: "r"(dst_u32), "l"(src_ptr))
#define CPCOMMIT() asm volatile("cp.async.commit_group;")
#define CPWAIT0() asm volatile("cp.async.wait_group 0;")

// ---------------- prep: copy hidden->state AND build bf16 hi/lo split -------
__global__ void prep_kernel(const float* __restrict__ hidden) {
    size_t idx = (size_t)blockIdx.x * 256 + threadIdx.x;   // 8192*256
    int r = (int)(idx >> 8);
    int qq = (int)(idx & 255);
    int ch = qq >> 3, c4 = (qq & 7) * 4;   // 32 chunks of 32 k
    size_t goff = (size_t)r * Hc + ch * 32 + c4;
    float4 v = *(const float4*)&hidden[goff];
    *(float4*)&g_state[goff] = v;
    float vv[4] = {v.x, v.y, v.z, v.w};
    __nv_bfloat16 h[4], l[4];
#pragma unroll
    for (int j = 0; j < 4; ++j) {
        h[j] = __float2bfloat16_rn(vv[j]);
        l[j] = __float2bfloat16_rn(vv[j] - __bfloat162float(h[j]));
    }
    size_t base = (size_t)r * 2048 + ch * 64;
    *(uint32_t*)&g_Acat[base + c4]          = bf2pack(h[0], h[1]);
    *(uint32_t*)&g_Acat[base + c4 + 2]      = bf2pack(h[2], h[3]);
    *(uint32_t*)&g_Acat[base + 32 + c4]     = bf2pack(l[0], l[1]);
    *(uint32_t*)&g_Acat[base + 32 + c4 + 2] = bf2pack(l[2], l[3]);
}

__global__ void zero_energy_kernel() {
    if (threadIdx.x < Bc) g_energy[threadIdx.x] = 0.f;
}

// ---------------- Wq transpose + hi/lo split --------------------------------
__global__ void convertW_kernel(const float* __restrict__ W) {
    __shared__ float tile[32][33];
    int kb = blockIdx.x, nb = blockIdx.y;
    int tx = threadIdx.x & 31, ty = threadIdx.x >> 5;   // 32 x 8
#pragma unroll
    for (int j = 0; j < 4; ++j) {
        int k = ty + j * 8;
        tile[k][tx] = W[(size_t)(kb * 32 + k) * Hc + nb * 32 + tx];
    }
    __syncthreads();
#pragma unroll
    for (int j = 0; j < 4; ++j) {
        int n = ty + j * 8;
        float x = tile[tx][n];
        __nv_bfloat16 h = __float2bfloat16_rn(x);
        __nv_bfloat16 l = __float2bfloat16_rn(x - __bfloat162float(h));
        size_t base = (size_t)(nb * 32 + n) * 2048 + kb * 64;
        g_Wt[base + tx]      = h;
        g_Wt[base + 32 + tx] = l;
    }
}

// ---------------- GEMM v4: 64x128 tile, 256 thr, cp.async, 3 CTAs/SM --------
#define BM4 64
#define BN4 128
#define SST 72   // smem row stride (bf16), conflict-free fragment loads
__global__ void __launch_bounds__(256, 3) gemm_mma_kernel(const float* __restrict__ bias) {
    __shared__ __nv_bfloat16 sA[BM4 * SST];   // 9.2 KB
    __shared__ __nv_bfloat16 sB[BN4 * SST];   // 18.4 KB
    int tid = threadIdx.x;
    int wid = tid >> 5, lane = tid & 31;
    int g = lane >> 2, tg = lane & 3;
    int wm = wid & 1, wn = wid >> 1;          // 2 x 4 warps, warp tile 32x32
    int m0 = blockIdx.y * BM4, n0 = blockIdx.x * BN4;
    float acc[2][4][4] = {};
    const int AO[6] = {0, 16, 32, 48, 0, 16};   // hi,hi | lo,lo | hi,hi
    const int BO[6] = {0, 16, 0, 16, 32, 48};   // hi,hi | hi,hi | lo,lo

    // staging: sA 64 rows x 8 segs(16B) -> 2 segs/thread; sB 128 rows x 8 -> 4
    int rA = tid >> 2, sgA = (tid & 3) * 2;
    int rB = tid >> 1, sgB = (tid & 1) * 4;
    const __nv_bfloat16* pa = &g_Acat[(size_t)(m0 + rA) * 2048 + sgA * 8];
    const __nv_bfloat16* pb = &g_Wt[(size_t)(n0 + rB) * 2048 + sgB * 8];
    uint32_t dA = (uint32_t)__cvta_generic_to_shared(&sA[rA * SST + sgA * 8]);
    uint32_t dB = (uint32_t)__cvta_generic_to_shared(&sB[rB * SST + sgB * 8]);

    for (int ch = 0; ch < 32; ++ch) {
        const __nv_bfloat16* a = pa + ch * 64;
        const __nv_bfloat16* b = pb + ch * 64;
        CP16(dA, a);
        CP16(dA + 16, a + 8);
        CP16(dB, b);
        CP16(dB + 16, b + 8);
        CP16(dB + 32, b + 16);
        CP16(dB + 48, b + 24);
        CPCOMMIT();
        CPWAIT0();
        __syncthreads();
#pragma unroll
        for (int s = 0; s < 6; ++s) {
            int ka = AO[s] + 2 * tg, kb = BO[s] + 2 * tg;
            uint32_t af[2][4], bf[4][2];
#pragma unroll
            for (int mt = 0; mt < 2; ++mt) {
                int row = wm * 32 + mt * 16 + g;
                af[mt][0] = *(const uint32_t*)&sA[row * SST + ka];
                af[mt][1] = *(const uint32_t*)&sA[(row + 8) * SST + ka];
                af[mt][2] = *(const uint32_t*)&sA[row * SST + ka + 8];
                af[mt][3] = *(const uint32_t*)&sA[(row + 8) * SST + ka + 8];
            }
#pragma unroll
            for (int nt = 0; nt < 4; ++nt) {
                int col = wn * 32 + nt * 8 + g;
                bf[nt][0] = *(const uint32_t*)&sB[col * SST + kb];
                bf[nt][1] = *(const uint32_t*)&sB[col * SST + kb + 8];
            }
#pragma unroll
            for (int mt = 0; mt < 2; ++mt)
#pragma unroll
                for (int nt = 0; nt < 4; ++nt)
                    asm volatile(
                        "mma.sync.aligned.m16n8k16.row.col.f32.bf16.bf16.f32 "
                        "{%0,%1,%2,%3}, {%4,%5,%6,%7}, {%8,%9}, {%0,%1,%2,%3};"
                        : "+f"(acc[mt][nt][0]), "+f"(acc[mt][nt][1]),
                          "+f"(acc[mt][nt][2]), "+f"(acc[mt][nt][3])
                        : "r"(af[mt][0]), "r"(af[mt][1]), "r"(af[mt][2]), "r"(af[mt][3]),
                          "r"(bf[nt][0]), "r"(bf[nt][1]));
        }
        __syncthreads();
    }
#pragma unroll
    for (int mt = 0; mt < 2; ++mt)
#pragma unroll
        for (int nt = 0; nt < 4; ++nt) {
            int row = m0 + wm * 32 + mt * 16 + g;
            int col = n0 + wn * 32 + nt * 8 + 2 * tg;
            float2 bi = *(const float2*)&bias[col];
            float2 v0 = {acc[mt][nt][0] + bi.x, acc[mt][nt][1] + bi.y};
            float2 v1 = {acc[mt][nt][2] + bi.x, acc[mt][nt][3] + bi.y};
            *(float2*)&g_q[(size_t)row * Hc + col] = v0;
            *(float2*)&g_q[(size_t)(row + 8) * Hc + col] = v1;
        }
}

// ---------------- dots: 9 sliding dot-products per node (read-only) ---------
#define DS 32
__global__ void __launch_bounds__(512) dots2_kernel(const float* __restrict__ st) {
    __shared__ float smo[DS + 8][128];
    int blk = blockIdx.x;
    int b = blk >> 6;
    int s0 = (blk & 63) * DS;
    int warp = threadIdx.x >> 5, lane = threadIdx.x & 31;
    int r0 = warp * 2;
    const float* sbase = st + (size_t)b * Sc * Hc;
    float acc[2][9];
#pragma unroll
    for (int rr = 0; rr < 2; ++rr)
#pragma unroll
        for (int d = 0; d < 9; ++d) acc[rr][d] = 0.f;

    for (int hc = 0; hc < Hc / 128; ++hc) {
        int h0 = hc * 128;
        for (int idx = threadIdx.x; idx < (DS + 8) * 32; idx += 512) {
            int r = idx >> 5, c4 = idx & 31;
            int s = s0 + r; if (s >= Sc) s = Sc - 1;
            *(float4*)&smo[r][c4 * 4] =
                *(const float4*)&sbase[(size_t)s * Hc + h0 + c4 * 4];
        }
        __syncthreads();
#pragma unroll
        for (int u = 0; u < 4; ++u) {
            int c = lane + u * 32;
            float xv[10];
#pragma unroll
            for (int t = 0; t < 10; ++t) xv[t] = smo[r0 + t][c];
#pragma unroll
            for (int rr = 0; rr < 2; ++rr)
#pragma unroll
                for (int d = 0; d < 9; ++d)
                    acc[rr][d] = fmaf(xv[rr], xv[rr + d], acc[rr][d]);
        }
        __syncthreads();
    }
#pragma unroll
    for (int rr = 0; rr < 2; ++rr) {
        int i = s0 + r0 + rr;
#pragma unroll
        for (int d = 0; d < 9; ++d) {
            float v = acc[rr][d];
#pragma unroll
            for (int o = 16; o; o >>= 1) v += __shfl_xor_sync(0xffffffffu, v, o);
            if (lane == 0) g_dots[((size_t)b * Sc + i) * 9 + d] = v;
        }
    }
}

// ---------------- mu: one warp per edge -------------------------------------
__global__ void mu_kernel(const float* __restrict__ W1, const float* __restrict__ b1,
                          const float* __restrict__ W2, const float* __restrict__ b2) {
    int gw = (blockIdx.x * blockDim.x + threadIdx.x) >> 5;
    int lane = threadIdx.x & 31;
    if (gw >= Bc * Sc * Rc) return;
    int dm = gw & 7;
    int i = (gw >> 3) % Sc;
    int b = gw / (Rc * Sc);
    int d = dm + 1;
    if (i + d >= Sc) return;
    const float* dots = &g_dots[(size_t)b * Sc * 9];
    float nii = dots[i * 9 + 0];
    float njj = dots[(i + d) * 9 + 0];
    float dij = dots[i * 9 + d];
    float dist = sqrtf(fmaxf(nii + njj - 2.f * dij, 0.f));
    float ni = fmaxf(sqrtf(nii), 1e-6f);
    float nj = fmaxf(sqrtf(njj), 1e-6f);
    float cosv = dij / (ni * nj);
    float acc = 0.f;
#pragma unroll
    for (int u = 0; u < INNERc / 32; ++u) {
        int m = lane + u * 32;
        float x = fmaf(dist, W1[m], fmaf(cosv, W1[INNERc + m], b1[m]));
        float g = 0.5f * x * (1.f + erff(x * 0.70710678118654752f));
        acc = fmaf(g, W2[m], acc);
    }
#pragma unroll
    for (int o = 16; o; o >>= 1) acc += __shfl_xor_sync(0xffffffffu, acc, o);
    if (lane == 0) {
        float z = acc + b2[0];
        float sp = fmaxf(z, 0.f) + log1pf(expf(-fabsf(z)));
        float mu = fminf(sp + 1e-5f, 10.f);
        g_mu[((size_t)b * Sc + i) * Rc + dm] = mu;
    }
}

// ---------------- invs ------------------------------------------------------
__global__ void invs_kernel() {
    int idx = blockIdx.x * blockDim.x + threadIdx.x;
    if (idx >= Bc * Sc) return;
    int b = idx / Sc, i = idx % Sc;
    const float* mu = &g_mu[(size_t)b * Sc * Rc];
    float deg = 0.f;
#pragma unroll
    for (int dm = 0; dm < Rc; ++dm) {
        int d = dm + 1;
        if (i + d < Sc) deg += mu[i * Rc + dm];
        if (i - d >= 0) deg += mu[(i - d) * Rc + dm];
    }
    g_invs[idx] = 1.f / sqrtf(fmaxf(deg, 1e-6f));
}

// ---------------- fused update + smooth (ping-pong in/out) ------------------
// out(i) = smooth(t)(i),  t(i) = s(i) - eta*(lap(i) - q(i)), i in [s0, s0+US2)
// needs t rows [s0-1, s0+US2] -> state rows [s0-9, s0+US2+8]
#define US2 64
#define UH2 64
__global__ void __launch_bounds__(256) upsm_kernel(const float* __restrict__ sin_,
                                                   float* __restrict__ sout,
                                                   float eta) {
    __shared__ float tile[US2 + 18][UH2];   // 82 x 64
    __shared__ float tt[US2 + 2][UH2];      // 66 x 64
    __shared__ float coef[US2 + 2][16];
    __shared__ float cself[US2 + 2];
    int chunk = blockIdx.x;
    int b = chunk >> 5;                 // Sc/US2 = 32 chunks per batch
    int s0 = (chunk & 31) * US2;
    int h0 = blockIdx.y * UH2;
    const float* sbase = sin_ + (size_t)b * Sc * Hc;
    const float* qbase = g_q + (size_t)b * Sc * Hc;
    float* obase = sout + (size_t)b * Sc * Hc;

    for (int idx = threadIdx.x; idx < (US2 + 18) * (UH2 / 4); idx += 256) {
        int r = idx / (UH2 / 4), c4 = (idx % (UH2 / 4)) * 4;
        int s = s0 - 9 + r;
        float4 v = make_float4(0.f, 0.f, 0.f, 0.f);
        if (s >= 0 && s < Sc) v = *(const float4*)&sbase[(size_t)s * Hc + h0 + c4];
        *(float4*)&tile[r][c4] = v;
    }
    const float* mu = &g_mu[(size_t)b * Sc * Rc];
    const float* invs = &g_invs[(size_t)b * Sc];
    for (int idx = threadIdx.x; idx < (US2 + 2) * 16; idx += 256) {
        int tr = idx >> 4, dd = idx & 15;
        int i = s0 - 1 + tr;
        float c = 0.f;
        if (i >= 0 && i < Sc) {
            if (dd < 8) {
                int d = dd + 1;
                if (i + d < Sc) c = mu[i * Rc + dd] * invs[i] * invs[i + d];
            } else {
                int d = dd - 7;
                if (i - d >= 0) c = mu[(i - d) * Rc + (d - 1)] * invs[i] * invs[i - d];
            }
        }
        coef[tr][dd] = c;
    }
    __syncthreads();
    if (threadIdx.x < US2 + 2) {
        float s = 0.f;
#pragma unroll
        for (int dd = 0; dd < 16; ++dd) s += coef[threadIdx.x][dd];
        cself[threadIdx.x] = s;
    }
    __syncthreads();

    int warp = threadIdx.x >> 5, lane = threadIdx.x & 31;
    int c = lane * 2;
    for (int tr = warp; tr < US2 + 2; tr += 8) {
        int i = s0 - 1 + tr;
        if (i < 0 || i >= Sc) continue;
        float2 s = *(float2*)&tile[tr + 8][c];
        float2 a = make_float2(0.f, 0.f);
#pragma unroll
        for (int dd = 0; dd < 16; ++dd) {
            float cf = coef[tr][dd];
            int roff = (dd < 8) ? (dd + 1) : -(dd - 7);
            float2 n = *(float2*)&tile[tr + 8 + roff][c];
            a.x = fmaf(cf, n.x, a.x);
            a.y = fmaf(cf, n.y, a.y);
        }
        float cs = cself[tr];
        float2 q = *(const float2*)&qbase[(size_t)i * Hc + h0 + c];
        float2 t;
        t.x = s.x - eta * (cs * s.x - a.x - q.x);
        t.y = s.y - eta * (cs * s.y - a.y - q.y);
        *(float2*)&tt[tr][c] = t;
    }
    __syncthreads();
    for (int il = warp; il < US2; il += 8) {
        int i = s0 + il;
        int tc = il + 1;
        int tl = (i == 0) ? 1 : il;
        int trr = (i == Sc - 1) ? il + 1 : il + 2;
        float2 xc = *(float2*)&tt[tc][c];
        float2 xl = *(float2*)&tt[tl][c];
        float2 xr = *(float2*)&tt[trr][c];
        float2 o;
        o.x = xc.x - 0.1f * (2.f * xc.x - xl.x - xr.x);
        o.y = xc.y - 0.1f * (2.f * xc.y - xl.y - xr.y);
        *(float2*)&obase[(size_t)i * Hc + h0 + c] = o;
    }
}

// ---------------- layernorm(state + hidden) ---------------------------------
__global__ void ln_kernel(const float* __restrict__ hidden,
                          const float* __restrict__ gamma,
                          const float* __restrict__ beta,
                          float* __restrict__ out) {
    int row = blockIdx.x;
    const float* s = g_state + (size_t)row * Hc;
    const float* h = hidden + (size_t)row * Hc;
    int tid = threadIdx.x;
    float v[4];
    float sum = 0.f, ss = 0.f;
#pragma unroll
    for (int k = 0; k < 4; ++k) {
        int c = tid + k * 256;
        float x = s[c] + h[c];
        v[k] = x;
        sum += x;
        ss += x * x;
    }
    __shared__ float r1[8], r2[8];
#pragma unroll
    for (int o = 16; o; o >>= 1) {
        sum += __shfl_xor_sync(0xffffffffu, sum, o);
        ss += __shfl_xor_sync(0xffffffffu, ss, o);
    }
    if ((tid & 31) == 0) { r1[tid >> 5] = sum; r2[tid >> 5] = ss; }
    __syncthreads();
    if (tid < 32) {
        float a = (tid < 8) ? r1[tid] : 0.f;
        float bb = (tid < 8) ? r2[tid] : 0.f;
#pragma unroll
        for (int o = 4; o; o >>= 1) {
            a += __shfl_xor_sync(0xffffffffu, a, o);
            bb += __shfl_xor_sync(0xffffffffu, bb, o);
        }
        if (tid == 0) { r1[0] = a; r2[0] = bb; }
    }
    __syncthreads();
    float mean = r1[0] * (1.f / Hc);
    float var = r2[0] * (1.f / Hc) - mean * mean;
    float is = rsqrtf(var + 1e-5f);
#pragma unroll
    for (int k = 0; k < 4; ++k) {
        int c = tid + k * 256;
        out[(size_t)row * Hc + c] = (v[k] - mean) * is * gamma[c] + beta[c];
    }
}

// ---------------- energy ----------------------------------------------------
__global__ void energy_kernel() {
    int b = blockIdx.y;
    int t = blockIdx.x * blockDim.x + threadIdx.x;
    float e = 0.f;
    if (t < Sc * Rc) {
        int dm = t & 7;
        int i = t >> 3;
        int d = dm + 1;
        if (i + d < Sc) {
            const float* dots = &g_dots[(size_t)b * Sc * 9];
            float diff2 = dots[i * 9] + dots[(i + d) * 9] - 2.f * dots[i * 9 + d];
            e = g_mu[((size_t)b * Sc + i) * Rc + dm] * diff2;
        }
    }
    __shared__ float sred[256];
    sred[threadIdx.x] = e;
    __syncthreads();
    for (int o = 128; o; o >>= 1) {
        if (threadIdx.x < o) sred[threadIdx.x] += sred[threadIdx.x + o];
        __syncthreads();
    }
    if (threadIdx.x == 0) atomicAdd(&g_energy[b], sred[0]);
}

__global__ void finalize_energy_kernel(float* __restrict__ out) {
    if (threadIdx.x < Bc)
        out[(size_t)Bc * Sc * Hc + threadIdx.x] = 0.5f * g_energy[threadIdx.x];
}

// ---------------- launch ----------------------------------------------------
extern "C" void kernel_launch(void* const* d_in, const int* in_sizes, int n_in,
                              void* d_out, int out_size) {
    const float* hidden = (const float*)d_in[0];
    const float* Wq = (const float*)d_in[3];
    const float* bq = (const float*)d_in[4];
    const float* W1 = (const float*)d_in[5];
    const float* b1 = (const float*)d_in[6];
    const float* W2 = (const float*)d_in[7];
    const float* b2 = (const float*)d_in[8];
    const float* gamma = (const float*)d_in[9];
    const float* beta = (const float*)d_in[10];
    float* out = (float*)d_out;

    prep_kernel<<<8192, 256>>>(hidden);
    convertW_kernel<<<dim3(32, 32), 256>>>(Wq);
    gemm_mma_kernel<<<dim3(Hc / BN4, (Bc * Sc) / BM4), 256>>>(bq);

    float* bufA;
    float* bufB;
    cudaGetSymbolAddress((void**)&bufA, g_state);
    cudaGetSymbolAddress((void**)&bufB, g_tmp);
    float* bufs[2] = {bufA, bufB};

    dots2_kernel<<<Bc * (Sc / DS), 512>>>(bufs[0]);
    for (int k = 0; k < 4; ++k) {
        double eta_d = 0.1 * pow(0.9, (double)k);
        float eta = (float)eta_d;
        mu_kernel<<<(Bc * Sc * Rc * 32) / 256, 256>>>(W1, b1, W2, b2);
        invs_kernel<<<(Bc * Sc) / 256, 256>>>();
        upsm_kernel<<<dim3(Bc * (Sc / US2), Hc / UH2), 256>>>(bufs[k & 1],
                                                              bufs[(k + 1) & 1], eta);
        dots2_kernel<<<Bc * (Sc / DS), 512>>>(bufs[(k + 1) & 1]);
    }

    zero_energy_kernel<<<1, 32>>>();
    energy_kernel<<<dim3((Sc * Rc + 255) / 256, Bc), 256>>>();
    ln_kernel<<<Bc * Sc, 256>>>(hidden, gamma, beta, out);   // final in g_state
    finalize_energy_kernel<<<1, 32>>>(out);
}